// round 1
// baseline (speedup 1.0000x reference)
#include <cuda_runtime.h>
#include <cstdint>

// Problem constants
#define N_TOK   131072          // 32*4096 tokens
#define DIM     64
#define NE      512
#define ROWF    80              // padded floats per smem code row (320B: 2-way fill conflicts, 16B aligned)
#define SMEM_E_BYTES (NE * ROWF * 4)          // 163840
#define SMEM_TOTAL   (SMEM_E_BYTES + NE * 4)  // + sq_e[512] = 165888 B

// Output layout (all fp32, concatenated in reference return order)
#define OUT_Q     0ull          // quantize_st: 8388608
#define OUT_DIFF  8388608ull    // diff: 1
#define OUT_IND   8388609ull    // embed_ind: 131072
#define OUT_EMB   8519681ull    // new_embed: 32768
#define OUT_CS    8552449ull    // new_cluster_size: 512
#define OUT_AVG   8552961ull    // new_embed_avg: 32768

// Scratch (device globals — no allocation allowed)
__device__ float        g_embed_sum[DIM * NE];
__device__ unsigned int g_hist[NE];
__device__ double       g_diff;

static __device__ __forceinline__ unsigned long long fma2(unsigned long long a,
                                                          unsigned long long b,
                                                          unsigned long long c) {
    unsigned long long d;
    asm("fma.rn.f32x2 %0, %1, %2, %3;" : "=l"(d) : "l"(a), "l"(b), "l"(c));
    return d;
}
static __device__ __forceinline__ unsigned long long add2(unsigned long long a,
                                                          unsigned long long b) {
    unsigned long long d;
    asm("add.rn.f32x2 %0, %1, %2;" : "=l"(d) : "l"(a), "l"(b));
    return d;
}
static __device__ __forceinline__ float lo32(unsigned long long v) {
    return __uint_as_float((unsigned)v);
}
static __device__ __forceinline__ float hi32(unsigned long long v) {
    return __uint_as_float((unsigned)(v >> 32));
}

__global__ void vq_init() {
    int i = blockIdx.x * blockDim.x + threadIdx.x;
    if (i < DIM * NE) g_embed_sum[i] = 0.0f;
    if (i < NE)       g_hist[i] = 0u;
    if (i == 0)       g_diff = 0.0;
}

__global__ __launch_bounds__(512, 1)
void vq_main(const float* __restrict__ x, const float* __restrict__ embed,
             float* __restrict__ out) {
    extern __shared__ float sm[];
    float* sE = sm;               // [NE][ROWF] code rows, dim-contiguous
    float* sq = sm + NE * ROWF;   // [NE] ||E_e||^2
    const int tid = threadIdx.x;

    // Fill SMEM codebook transposed: embed is [d][e] (e fastest) -> sE[e][d].
    // Global reads fully coalesced; stores stride 320B -> 2-way conflicts (one-time).
    for (int idx = tid; idx < DIM * NE; idx += 512) {
        int d = idx >> 9;
        int e = idx & (NE - 1);
        sE[e * ROWF + d] = embed[idx];
    }
    __syncthreads();

    // ||E_e||^2 per code (fp32, tiny magnitude — ordering irrelevant to argmin grid)
    {
        const float* r = sE + tid * ROWF;
        float s = 0.0f;
#pragma unroll
        for (int d = 0; d < DIM; d++) s = __fmaf_rn(r[d], r[d], s);
        sq[tid] = s;
    }
    __syncthreads();

    // One token per thread; grid-stride over tokens.
    for (int tok = blockIdx.x * 512 + tid; tok < N_TOK; tok += gridDim.x * 512) {
        // Load f as 32 packed f32x2 pairs (f[2i], f[2i+1])
        unsigned long long fq[32];
        const ulonglong2* xr = (const ulonglong2*)(x + (size_t)tok * DIM);
#pragma unroll
        for (int i = 0; i < 16; i++) {
            ulonglong2 v = xr[i];
            fq[2 * i]     = v.x;
            fq[2 * i + 1] = v.y;
        }

        // ||f||^2 (constant per token — shared across all codes, cannot flip argmin)
        unsigned long long s2a = 0ull, s2b = 0ull;
#pragma unroll
        for (int i = 0; i < 32; i += 2) {
            s2a = fma2(fq[i],     fq[i],     s2a);
            s2b = fma2(fq[i + 1], fq[i + 1], s2b);
        }
        unsigned long long s2 = add2(s2a, s2b);
        float sumf = lo32(s2) + hi32(s2);

        float best = 3.4028235e38f;
        int   bi   = 0;

        // 512 codes: per code 16x LDS.128 (broadcast) + 32x FFMA2 -> fp32-pipe bound
        for (int e = 0; e < NE; e++) {
            const char* rb = (const char*)sE + e * (ROWF * 4);
            unsigned long long a0 = 0ull, a1 = 0ull, a2 = 0ull, a3 = 0ull;
#pragma unroll
            for (int c = 0; c < 16; c += 2) {
                ulonglong2 v0 = *(const ulonglong2*)(rb + c * 16);
                ulonglong2 v1 = *(const ulonglong2*)(rb + c * 16 + 16);
                a0 = fma2(fq[2 * c],     v0.x, a0);
                a1 = fma2(fq[2 * c + 1], v0.y, a1);
                a2 = fma2(fq[2 * c + 2], v1.x, a2);
                a3 = fma2(fq[2 * c + 3], v1.y, a3);
            }
            unsigned long long s = add2(add2(a0, a2), add2(a1, a3));
            float dot  = lo32(s) + hi32(s);
            // Match reference rounding: (sumf - 2*dot) then + ||E||^2
            float t    = __fmaf_rn(-2.0f, dot, sumf);
            float dist = t + sq[e];
            if (dist < best) { best = dist; bi = e; }  // strict < keeps first index (argmin tie rule)
        }

        const int ind = bi;
        out[OUT_IND + tok] = (float)ind;
        atomicAdd(&g_hist[ind], 1u);

        // Gather code row, write quantize_st, accumulate diff + segment sum
        const float* qr = sE + ind * ROWF;
        float4* oq = (float4*)(out + OUT_Q + (size_t)tok * DIM);
        float dsum = 0.0f;
#pragma unroll
        for (int i = 0; i < 16; i++) {
            float fx0 = lo32(fq[2 * i]),     fx1 = hi32(fq[2 * i]);
            float fx2 = lo32(fq[2 * i + 1]), fx3 = hi32(fq[2 * i + 1]);
            float q0 = qr[4 * i + 0], q1 = qr[4 * i + 1];
            float q2 = qr[4 * i + 2], q3 = qr[4 * i + 3];
            float d0 = q0 - fx0, d1 = q1 - fx1, d2 = q2 - fx2, d3 = q3 - fx3;
            dsum += d0 * d0 + d1 * d1 + d2 * d2 + d3 * d3;
            float4 st;                       // quantize_st = x + (q - x), reference rounding
            st.x = fx0 + d0; st.y = fx1 + d1; st.z = fx2 + d2; st.w = fx3 + d3;
            oq[i] = st;
            atomicAdd(&g_embed_sum[(4 * i + 0) * NE + ind], fx0);
            atomicAdd(&g_embed_sum[(4 * i + 1) * NE + ind], fx1);
            atomicAdd(&g_embed_sum[(4 * i + 2) * NE + ind], fx2);
            atomicAdd(&g_embed_sum[(4 * i + 3) * NE + ind], fx3);
        }
        // diff partial: warp-reduce then one double atomic per warp
#pragma unroll
        for (int o = 16; o; o >>= 1) dsum += __shfl_xor_sync(0xffffffffu, dsum, o);
        if ((tid & 31) == 0) atomicAdd(&g_diff, (double)dsum);
    }
}

__global__ void vq_fin(const float* __restrict__ cs_in, const float* __restrict__ ea_in,
                       float* __restrict__ out) {
    __shared__ float sn[512];
    const int e = threadIdx.x;

    float h   = (float)g_hist[e];
    float ncs = cs_in[e] * 0.99f + 0.01f * h;   // new_cluster_size
    out[OUT_CS + e] = ncs;

    sn[e] = ncs;
    __syncthreads();
    for (int o = 256; o; o >>= 1) {
        if (e < o) sn[e] += sn[e + o];
        __syncthreads();
    }
    const float n   = sn[0];
    const float csn = (ncs + 1e-5f) / (n + 0.00512f) * n;  // Laplace-smoothed cluster size

#pragma unroll 4
    for (int d = 0; d < DIM; d++) {
        int idx = d * NE + e;
        float avg = ea_in[idx] * 0.99f + 0.01f * g_embed_sum[idx];
        out[OUT_AVG + idx] = avg;              // new_embed_avg
        out[OUT_EMB + idx] = avg / csn;        // new_embed
    }

    if (e == 0) out[OUT_DIFF] = (float)(g_diff * (1.0 / 8388608.0));
}

extern "C" void kernel_launch(void* const* d_in, const int* in_sizes, int n_in,
                              void* d_out, int out_size) {
    const float* x     = (const float*)d_in[0];
    const float* embed = (const float*)d_in[1];
    const float* cs    = (const float*)d_in[2];
    const float* ea    = (const float*)d_in[3];
    float* out = (float*)d_out;

    cudaFuncSetAttribute(vq_main, cudaFuncAttributeMaxDynamicSharedMemorySize, SMEM_TOTAL);

    vq_init<<<64, 512>>>();
    vq_main<<<148, 512, SMEM_TOTAL>>>(x, embed, out);
    vq_fin<<<1, 512>>>(cs, ea, out);
}